// round 1
// baseline (speedup 1.0000x reference)
#include <cuda_runtime.h>
#include <cuda_bf16.h>
#include <cstdint>

#define D 256
#define BM 128
#define BNT 128
#define LDS_ROW 264          // 256 + 8 bf16 pad -> conflict-free ldmatrix
#define MAXN_PAD 100352      // multiple of 128, >= 100000
#define MAXB 1024
#define NSPLIT 37            // 8 qblocks * 37 = 296 CTAs = 2 waves on 148 SMs

__device__ __nv_bfloat16 g_tn[(size_t)MAXN_PAD * D];
__device__ __nv_bfloat16 g_qn[(size_t)MAXB * D];
__device__ float g_l[MAXB];
__device__ float g_s[MAXB];

// ---------------- prep kernels: L2-normalize into bf16 ----------------

__global__ void prep_q_kernel(const float* __restrict__ q, int B) {
    int gtid = blockIdx.x * blockDim.x + threadIdx.x;
    int row  = gtid >> 5;
    int lane = threadIdx.x & 31;
    if (gtid < MAXB) { g_l[gtid] = 0.f; g_s[gtid] = 0.f; }
    if (row >= B) return;
    const float* src = q + (size_t)row * D;
    float v[8];
    float ss = 0.f;
#pragma unroll
    for (int i = 0; i < 8; i++) { v[i] = src[lane * 8 + i]; ss += v[i] * v[i]; }
#pragma unroll
    for (int o = 16; o > 0; o >>= 1) ss += __shfl_xor_sync(0xffffffffu, ss, o);
    float inv = 1.f / fmaxf(sqrtf(ss), 1e-12f);
    __nv_bfloat16* dst = g_qn + (size_t)row * D;
#pragma unroll
    for (int i = 0; i < 8; i++) dst[lane * 8 + i] = __float2bfloat16(v[i] * inv);
}

__global__ void prep_t_kernel(const float* __restrict__ t, int N, int Npad) {
    int gtid = blockIdx.x * blockDim.x + threadIdx.x;
    int row  = gtid >> 5;
    int lane = threadIdx.x & 31;
    if (row >= Npad) return;
    __nv_bfloat16* dst = g_tn + (size_t)row * D;
    if (row >= N) {
#pragma unroll
        for (int i = 0; i < 8; i++) dst[lane * 8 + i] = __float2bfloat16(0.f);
        return;
    }
    const float* src = t + (size_t)row * D;
    float v[8];
    float ss = 0.f;
#pragma unroll
    for (int i = 0; i < 8; i++) { v[i] = src[lane * 8 + i]; ss += v[i] * v[i]; }
#pragma unroll
    for (int o = 16; o > 0; o >>= 1) ss += __shfl_xor_sync(0xffffffffu, ss, o);
    float inv = 1.f / fmaxf(sqrtf(ss), 1e-12f);
#pragma unroll
    for (int i = 0; i < 8; i++) dst[lane * 8 + i] = __float2bfloat16(v[i] * inv);
}

// ---------------- main kernel: GEMM + fused softmax-sum epilogue ----------------

__global__ __launch_bounds__(256, 1) void knn_main_kernel(int B, int N, int tilesTotal) {
    extern __shared__ unsigned char smem_raw[];
    __nv_bfloat16* Qs = (__nv_bfloat16*)smem_raw;
    __nv_bfloat16* Ts = (__nv_bfloat16*)(smem_raw + (size_t)BM * LDS_ROW * 2);
    float* sm_l = (float*)(smem_raw + (size_t)2 * BM * LDS_ROW * 2);
    float* sm_s = sm_l + BM;

    const int tid  = threadIdx.x;
    const int lane = tid & 31;
    const int warp = tid >> 5;
    const int wm   = warp >> 2;   // 0..1  -> 64-row half
    const int wn   = warp & 3;    // 0..3  -> 32-col slice
    const int qb   = blockIdx.x;
    const int qbase = qb * BM;

    // Load Q block [128 x 256] bf16 -> smem (padded rows)
    {
        const uint4* src = (const uint4*)(g_qn + (size_t)qbase * D);
#pragma unroll
        for (int i = 0; i < 16; i++) {
            int idx = tid + i * 256;        // 0..4095, 32 uint4 per row
            int r   = idx >> 5;
            int c8  = idx & 31;
            uint4 val = src[r * 32 + c8];
            *(uint4*)(Qs + r * LDS_ROW + c8 * 8) = val;
        }
    }
    if (tid < BM) { sm_l[tid] = 0.f; sm_s[tid] = 0.f; }

    const int t0 = (int)(((long long)blockIdx.y       * tilesTotal) / gridDim.y);
    const int t1 = (int)(((long long)(blockIdx.y + 1) * tilesTotal) / gridDim.y);

    float lrow[4][2], srow[4][2];
#pragma unroll
    for (int mi = 0; mi < 4; mi++) {
        lrow[mi][0] = lrow[mi][1] = 0.f;
        srow[mi][0] = srow[mi][1] = 0.f;
    }

    const uint32_t QsB = (uint32_t)__cvta_generic_to_shared(Qs);
    const uint32_t TsB = (uint32_t)__cvta_generic_to_shared(Ts);

    const int aRow  = lane & 15;           // ldmatrix x4 row
    const int aCoff = (lane >> 4) * 8;     // +8 cols for upper 16 lanes
    const int bRow  = lane & 7;            // ldmatrix x2 row
    const int bCoff = ((lane >> 3) & 1) * 8;

    __syncthreads();

    for (int t = t0; t < t1; t++) {
        // Load T tile [128 x 256] bf16 -> smem
        {
            const uint4* src = (const uint4*)(g_tn + (size_t)t * BNT * D);
#pragma unroll
            for (int i = 0; i < 16; i++) {
                int idx = tid + i * 256;
                int r   = idx >> 5;
                int c8  = idx & 31;
                uint4 val = src[r * 32 + c8];
                *(uint4*)(Ts + r * LDS_ROW + c8 * 8) = val;
            }
        }
        __syncthreads();

        float acc[4][4][4];
#pragma unroll
        for (int mi = 0; mi < 4; mi++)
#pragma unroll
            for (int ni = 0; ni < 4; ni++)
#pragma unroll
                for (int j = 0; j < 4; j++) acc[mi][ni][j] = 0.f;

#pragma unroll
        for (int ks = 0; ks < 16; ks++) {
            const int kk = ks * 16;
            uint32_t a[4][4];
#pragma unroll
            for (int mi = 0; mi < 4; mi++) {
                uint32_t addr = QsB + (uint32_t)(((wm * 64 + mi * 16 + aRow) * LDS_ROW + kk + aCoff) << 1);
                asm volatile("ldmatrix.sync.aligned.m8n8.x4.shared.b16 {%0,%1,%2,%3}, [%4];"
                             : "=r"(a[mi][0]), "=r"(a[mi][1]), "=r"(a[mi][2]), "=r"(a[mi][3])
                             : "r"(addr));
            }
            uint32_t b[4][2];
#pragma unroll
            for (int ni = 0; ni < 4; ni++) {
                uint32_t addr = TsB + (uint32_t)(((wn * 32 + ni * 8 + bRow) * LDS_ROW + kk + bCoff) << 1);
                asm volatile("ldmatrix.sync.aligned.m8n8.x2.shared.b16 {%0,%1}, [%2];"
                             : "=r"(b[ni][0]), "=r"(b[ni][1])
                             : "r"(addr));
            }
#pragma unroll
            for (int mi = 0; mi < 4; mi++)
#pragma unroll
                for (int ni = 0; ni < 4; ni++) {
                    asm volatile(
                        "mma.sync.aligned.m16n8k16.row.col.f32.bf16.bf16.f32 "
                        "{%0,%1,%2,%3}, {%4,%5,%6,%7}, {%8,%9}, {%0,%1,%2,%3};"
                        : "+f"(acc[mi][ni][0]), "+f"(acc[mi][ni][1]),
                          "+f"(acc[mi][ni][2]), "+f"(acc[mi][ni][3])
                        : "r"(a[mi][0]), "r"(a[mi][1]), "r"(a[mi][2]), "r"(a[mi][3]),
                          "r"(b[ni][0]), "r"(b[ni][1]));
                }
        }

        // Fused epilogue: dist = sqrt(2-2c); e = exp(-10*dist); accumulate l, e*d
        const int nTileBase = t * BNT + wn * 32;
#pragma unroll
        for (int mi = 0; mi < 4; mi++)
#pragma unroll
            for (int ni = 0; ni < 4; ni++)
#pragma unroll
                for (int j = 0; j < 4; j++) {
                    int n = nTileBase + ni * 8 + ((lane & 3) << 1) + (j & 1);
                    if (n < N) {
                        float c    = acc[mi][ni][j];
                        float dist = sqrtf(fmaxf(2.f - 2.f * c, 0.f));
                        float e    = __expf(-10.f * dist);
                        int   h    = j >> 1;
                        lrow[mi][h] += e;
                        srow[mi][h]  = fmaf(e, dist, srow[mi][h]);
                    }
                }
        __syncthreads();   // protect Ts before next tile's load
    }

    // Reduce across the 4 lanes sharing a row, then into smem, then global
#pragma unroll
    for (int mi = 0; mi < 4; mi++)
#pragma unroll
        for (int h = 0; h < 2; h++) {
            float lv = lrow[mi][h], sv = srow[mi][h];
            lv += __shfl_xor_sync(0xffffffffu, lv, 1);
            lv += __shfl_xor_sync(0xffffffffu, lv, 2);
            sv += __shfl_xor_sync(0xffffffffu, sv, 1);
            sv += __shfl_xor_sync(0xffffffffu, sv, 2);
            if ((lane & 3) == 0) {
                int r = wm * 64 + mi * 16 + (lane >> 2) + 8 * h;
                atomicAdd(&sm_l[r], lv);
                atomicAdd(&sm_s[r], sv);
            }
        }
    __syncthreads();
    if (tid < BM) {
        atomicAdd(&g_l[qbase + tid], sm_l[tid]);
        atomicAdd(&g_s[qbase + tid], sm_s[tid]);
    }
}

__global__ void finalize_kernel(float* __restrict__ out, int B) {
    int i = blockIdx.x * blockDim.x + threadIdx.x;
    if (i < B) out[i] = g_s[i] / g_l[i];
}

// ---------------- launch ----------------

extern "C" void kernel_launch(void* const* d_in, const int* in_sizes, int n_in,
                              void* d_out, int out_size) {
    const float* q = (const float*)d_in[0];
    const float* t = (const float*)d_in[1];
    int B = in_sizes[0] / D;
    int N = in_sizes[1] / D;
    if (B > MAXB) B = MAXB;
    int Npad = ((N + BNT - 1) / BNT) * BNT;
    if (Npad > MAXN_PAD) Npad = MAXN_PAD;
    int tilesTotal = Npad / BNT;

    const int smemBytes = 2 * BM * LDS_ROW * 2 + 2 * BM * (int)sizeof(float);
    cudaFuncSetAttribute(knn_main_kernel,
                         cudaFuncAttributeMaxDynamicSharedMemorySize, smemBytes);

    prep_q_kernel<<<(B * 32 + 255) / 256, 256>>>(q, B);
    prep_t_kernel<<<(Npad * 32 + 255) / 256, 256>>>(t, N, Npad);

    int numQB = B / BM;
    if (numQB < 1) numQB = 1;
    knn_main_kernel<<<dim3(numQB, NSPLIT), 256, smemBytes>>>(B, N, tilesTotal);

    finalize_kernel<<<(B + 255) / 256, 256>>>((float*)d_out, B);
}

// round 3
// speedup vs baseline: 1.9787x; 1.9787x over previous
#include <cuda_runtime.h>
#include <cuda_bf16.h>
#include <cstdint>

#define D 256
#define BM 128
#define BNT 128
#define LDS_ROW 264          // 256 + 8 bf16 pad -> conflict-free ldmatrix
#define MAXN_PAD 100352      // multiple of 128, >= 100000
#define MAXB 1024
#define NSPLIT 37            // 8 qblocks * 37 = 296 CTAs = 2 waves on 148 SMs

#define TILE_BYTES_G (BNT * D * 2)            // 64 KB contiguous per tile in gmem
#define BUF_BYTES    (BM * LDS_ROW * 2)       // 67584 per smem buffer (padded rows)

__device__ __align__(256) __nv_bfloat16 g_tn[(size_t)MAXN_PAD * D];
__device__ __align__(256) __nv_bfloat16 g_qn[(size_t)MAXB * D];
__device__ float g_l[MAXB];
__device__ float g_s[MAXB];

// ---------------- tiny asm helpers ----------------

__device__ __forceinline__ void cp16(uint32_t dst, const void* src) {
    asm volatile("cp.async.cg.shared.global [%0], [%1], 16;" :: "r"(dst), "l"(src));
}
#define CP_COMMIT() asm volatile("cp.async.commit_group;" ::: "memory")
#define CP_WAIT1()  asm volatile("cp.async.wait_group 1;" ::: "memory")
#define CP_WAIT0()  asm volatile("cp.async.wait_group 0;" ::: "memory")

__device__ __forceinline__ float fsqrt_ap(float x) {
    float r; asm("sqrt.approx.f32 %0, %1;" : "=f"(r) : "f"(x)); return r;
}
__device__ __forceinline__ float fex2_ap(float x) {
    float r; asm("ex2.approx.f32 %0, %1;" : "=f"(r) : "f"(x)); return r;
}

// ---------------- prep kernels: L2-normalize into bf16 ----------------

__global__ void prep_q_kernel(const float* __restrict__ q, int B) {
    int gtid = blockIdx.x * blockDim.x + threadIdx.x;
    int row  = gtid >> 5;
    int lane = threadIdx.x & 31;
    if (gtid < MAXB) { g_l[gtid] = 0.f; g_s[gtid] = 0.f; }
    if (row >= B) return;
    const float* src = q + (size_t)row * D;
    float v[8], ss = 0.f;
#pragma unroll
    for (int i = 0; i < 8; i++) { v[i] = src[lane * 8 + i]; ss += v[i] * v[i]; }
#pragma unroll
    for (int o = 16; o > 0; o >>= 1) ss += __shfl_xor_sync(0xffffffffu, ss, o);
    float inv = 1.f / fmaxf(sqrtf(ss), 1e-12f);
    __nv_bfloat16* dst = g_qn + (size_t)row * D;
#pragma unroll
    for (int i = 0; i < 8; i++) dst[lane * 8 + i] = __float2bfloat16(v[i] * inv);
}

__global__ void prep_t_kernel(const float* __restrict__ t, int N, int Npad) {
    int gtid = blockIdx.x * blockDim.x + threadIdx.x;
    int row  = gtid >> 5;
    int lane = threadIdx.x & 31;
    if (row >= Npad) return;
    __nv_bfloat16* dst = g_tn + (size_t)row * D;
    if (row >= N) {
#pragma unroll
        for (int i = 0; i < 8; i++) dst[lane * 8 + i] = __float2bfloat16(0.f);
        return;
    }
    const float* src = t + (size_t)row * D;
    float v[8], ss = 0.f;
#pragma unroll
    for (int i = 0; i < 8; i++) { v[i] = src[lane * 8 + i]; ss += v[i] * v[i]; }
#pragma unroll
    for (int o = 16; o > 0; o >>= 1) ss += __shfl_xor_sync(0xffffffffu, ss, o);
    float inv = 1.f / fmaxf(sqrtf(ss), 1e-12f);
#pragma unroll
    for (int i = 0; i < 8; i++) dst[lane * 8 + i] = __float2bfloat16(v[i] * inv);
}

// ---------------- main kernel: pipelined GEMM + fused softmax-sum ----------------

__global__ __launch_bounds__(256, 1) void knn_main_kernel(int tilesTotal) {
    extern __shared__ unsigned char smem_raw[];
    __nv_bfloat16* Qs = (__nv_bfloat16*)smem_raw;
    __nv_bfloat16* Ts[2] = {
        (__nv_bfloat16*)(smem_raw + BUF_BYTES),
        (__nv_bfloat16*)(smem_raw + 2 * (size_t)BUF_BYTES)
    };
    float* sm_l = (float*)(smem_raw + 3 * (size_t)BUF_BYTES);
    float* sm_s = sm_l + BM;

    const int tid  = threadIdx.x;
    const int lane = tid & 31;
    const int warp = tid >> 5;
    const int wm   = warp >> 2;   // 0..1  -> 64-row half
    const int wn   = warp & 3;    // 0..3  -> 32-col slice
    const int qb   = blockIdx.x;
    const int qbase = qb * BM;

    const int t0 = (int)(((long long)blockIdx.y       * tilesTotal) / gridDim.y);
    const int t1 = (int)(((long long)(blockIdx.y + 1) * tilesTotal) / gridDim.y);
    const int cnt = t1 - t0;

    // per-thread copy coordinates: 4096 16B chunks per tile, 16 per thread
    const uint32_t TsAddr[2] = {
        (uint32_t)__cvta_generic_to_shared(Ts[0]),
        (uint32_t)__cvta_generic_to_shared(Ts[1])
    };

    // prologue: kick off tile t0 into buf 0 immediately
    if (cnt > 0) {
        const char* src = (const char*)g_tn + (size_t)t0 * TILE_BYTES_G;
#pragma unroll
        for (int i = 0; i < 16; i++) {
            int idx = tid + i * 256;
            int r = idx >> 5, c = idx & 31;
            cp16(TsAddr[0] + r * (LDS_ROW * 2) + c * 16, src + r * 512 + c * 16);
        }
        CP_COMMIT();
    }

    // Q block [128 x 256] -> smem (plain loads, once)
    {
        const uint4* src = (const uint4*)(g_qn + (size_t)qbase * D);
#pragma unroll
        for (int i = 0; i < 16; i++) {
            int idx = tid + i * 256;
            int r = idx >> 5, c8 = idx & 31;
            uint4 val = src[r * 32 + c8];
            *(uint4*)(Qs + r * LDS_ROW + c8 * 8) = val;
        }
    }
    if (tid < BM) { sm_l[tid] = 0.f; sm_s[tid] = 0.f; }

    float lrow[4][2], srow[4][2];
#pragma unroll
    for (int mi = 0; mi < 4; mi++) {
        lrow[mi][0] = lrow[mi][1] = 0.f;
        srow[mi][0] = srow[mi][1] = 0.f;
    }

    const uint32_t QsB = (uint32_t)__cvta_generic_to_shared(Qs);
    const int aRow  = lane & 15;
    const int aCoff = (lane >> 4) * 8;
    const int bRow  = lane & 7;
    const int bCoff = ((lane >> 3) & 1) * 8;

    for (int i = 0; i < cnt; i++) {
        const int s = i & 1;
        // issue next tile's copy into the other buffer (overlaps this tile's compute)
        if (i + 1 < cnt) {
            const char* src = (const char*)g_tn + (size_t)(t0 + i + 1) * TILE_BYTES_G;
            const uint32_t dstB = TsAddr[s ^ 1];
#pragma unroll
            for (int u = 0; u < 16; u++) {
                int idx = tid + u * 256;
                int r = idx >> 5, c = idx & 31;
                cp16(dstB + r * (LDS_ROW * 2) + c * 16, src + r * 512 + c * 16);
            }
            CP_COMMIT();
            CP_WAIT1();       // current tile's group done
        } else {
            CP_WAIT0();
        }
        __syncthreads();      // copies visible to all; prev compute done before reuse

        const uint32_t TsB = TsAddr[s];
        float acc[4][4][4];
#pragma unroll
        for (int mi = 0; mi < 4; mi++)
#pragma unroll
            for (int ni = 0; ni < 4; ni++)
#pragma unroll
                for (int j = 0; j < 4; j++) acc[mi][ni][j] = 0.f;

#pragma unroll
        for (int ks = 0; ks < 16; ks++) {
            const int kk = ks * 16;
            uint32_t a[4][4];
#pragma unroll
            for (int mi = 0; mi < 4; mi++) {
                uint32_t addr = QsB + (uint32_t)(((wm * 64 + mi * 16 + aRow) * LDS_ROW + kk + aCoff) << 1);
                asm volatile("ldmatrix.sync.aligned.m8n8.x4.shared.b16 {%0,%1,%2,%3}, [%4];"
                             : "=r"(a[mi][0]), "=r"(a[mi][1]), "=r"(a[mi][2]), "=r"(a[mi][3])
                             : "r"(addr));
            }
            uint32_t b[4][2];
#pragma unroll
            for (int ni = 0; ni < 4; ni++) {
                uint32_t addr = TsB + (uint32_t)(((wn * 32 + ni * 8 + bRow) * LDS_ROW + kk + bCoff) << 1);
                asm volatile("ldmatrix.sync.aligned.m8n8.x2.shared.b16 {%0,%1}, [%2];"
                             : "=r"(b[ni][0]), "=r"(b[ni][1])
                             : "r"(addr));
            }
#pragma unroll
            for (int mi = 0; mi < 4; mi++)
#pragma unroll
                for (int ni = 0; ni < 4; ni++) {
                    asm volatile(
                        "mma.sync.aligned.m16n8k16.row.col.f32.bf16.bf16.f32 "
                        "{%0,%1,%2,%3}, {%4,%5,%6,%7}, {%8,%9}, {%0,%1,%2,%3};"
                        : "+f"(acc[mi][ni][0]), "+f"(acc[mi][ni][1]),
                          "+f"(acc[mi][ni][2]), "+f"(acc[mi][ni][3])
                        : "r"(a[mi][0]), "r"(a[mi][1]), "r"(a[mi][2]), "r"(a[mi][3]),
                          "r"(b[ni][0]), "r"(b[ni][1]));
                }
        }

        // Fused epilogue — no masking (pad rows handled analytically in finalize)
#pragma unroll
        for (int mi = 0; mi < 4; mi++)
#pragma unroll
            for (int ni = 0; ni < 4; ni++)
#pragma unroll
                for (int j = 0; j < 4; j++) {
                    float c  = acc[mi][ni][j];
                    float x  = fmaxf(fmaf(-2.f, c, 2.f), 0.f);
                    float dd = fsqrt_ap(x);
                    float e  = fex2_ap(dd * -14.4269504089f);   // exp(-10*d)
                    int   h  = j >> 1;
                    lrow[mi][h] += e;
                    srow[mi][h]  = fmaf(e, dd, srow[mi][h]);
                }
        __syncthreads();   // everyone done reading Ts[s] before it is refilled
    }

    // Reduce across the 4 lanes sharing a row, then smem, then global
#pragma unroll
    for (int mi = 0; mi < 4; mi++)
#pragma unroll
        for (int h = 0; h < 2; h++) {
            float lv = lrow[mi][h], sv = srow[mi][h];
            lv += __shfl_xor_sync(0xffffffffu, lv, 1);
            lv += __shfl_xor_sync(0xffffffffu, lv, 2);
            sv += __shfl_xor_sync(0xffffffffu, sv, 1);
            sv += __shfl_xor_sync(0xffffffffu, sv, 2);
            if ((lane & 3) == 0) {
                int r = wm * 64 + mi * 16 + (lane >> 2) + 8 * h;
                atomicAdd(&sm_l[r], lv);
                atomicAdd(&sm_s[r], sv);
            }
        }
    __syncthreads();
    if (tid < BM) {
        atomicAdd(&g_l[qbase + tid], sm_l[tid]);
        atomicAdd(&g_s[qbase + tid], sm_s[tid]);
    }
}

__global__ void finalize_kernel(float* __restrict__ out, int B, int padCount) {
    int i = blockIdx.x * blockDim.x + threadIdx.x;
    if (i >= B) return;
    // pad rows contribute c=0 -> d0 = sqrt.approx(2), e0 = ex2.approx(-10*d0*log2e)
    float d0 = fsqrt_ap(2.0f);
    float e0 = fex2_ap(d0 * -14.4269504089f);
    float fp = (float)padCount;
    out[i] = (g_s[i] - fp * e0 * d0) / (g_l[i] - fp * e0);
}

// ---------------- launch ----------------

extern "C" void kernel_launch(void* const* d_in, const int* in_sizes, int n_in,
                              void* d_out, int out_size) {
    const float* q = (const float*)d_in[0];
    const float* t = (const float*)d_in[1];
    int B = in_sizes[0] / D;
    int N = in_sizes[1] / D;
    if (B > MAXB) B = MAXB;
    int Npad = ((N + BNT - 1) / BNT) * BNT;
    if (Npad > MAXN_PAD) Npad = MAXN_PAD;
    int tilesTotal = Npad / BNT;
    int padCount = tilesTotal * BNT - N;

    const int smemBytes = 3 * BUF_BYTES + 2 * BM * (int)sizeof(float);
    cudaFuncSetAttribute(knn_main_kernel,
                         cudaFuncAttributeMaxDynamicSharedMemorySize, smemBytes);

    prep_q_kernel<<<(B * 32 + 255) / 256, 256>>>(q, B);
    prep_t_kernel<<<(Npad * 32 + 255) / 256, 256>>>(t, N, Npad);

    int numQB = B / BM;
    if (numQB < 1) numQB = 1;
    knn_main_kernel<<<dim3(numQB, NSPLIT), 256, smemBytes>>>(tilesTotal);

    finalize_kernel<<<(B + 255) / 256, 256>>>((float*)d_out, B, padCount);
}